// round 11
// baseline (speedup 1.0000x reference)
#include <cuda_runtime.h>
#include <math.h>

// Problem constants (fixed by the reference).
#define BB 8
#define CC 16
#define NNDIM 512
#define EE 1024
#define POS_PER_B    (NNDIM * NNDIM)        // 262,144
#define GROUPS_PER_B (POS_PER_B / 4)        // 65,536 float4 groups per batch
#define BLKS_PER_BATCH 55
#define PBLK (BB * BLKS_PER_BATCH)          // 440 persistent blocks (one wave)
#define BSTRIDE (BLKS_PER_BATCH * 256)      // 14,080 groups
#define HASH_SZ 4096

// Globals (no dynamic allocation allowed).
__device__ double g_sum[BB];
__device__ double g_cnt[BB];
__device__ unsigned int g_done;

// ---------------------------------------------------------------------------
// 1) Correction kernel: one block per batch, one thread per edge.
//    Zeroes accumulators; exact last-write-wins dedup via O(E) shared hash;
//    accumulates (x_class0 - x_attr) for live, nonzero-attr, masked-valid
//    edges into g_sum[b].
// ---------------------------------------------------------------------------
__global__ void __launch_bounds__(EE) corr_kernel(
        const float* __restrict__ adj,
        const unsigned char* __restrict__ mask,
        const int* __restrict__ edge_index,
        const int* __restrict__ edge_attr) {
    __shared__ int s_slotkey[HASH_SZ];
    __shared__ int s_slotval[HASH_SZ];
    const int b = blockIdx.x;
    const int e = threadIdx.x;               // 0..EE-1

    if (e == 0) {
        g_sum[b] = 0.0;
        g_cnt[b] = 0.0;
        if (b == 0) g_done = 0u;
    }
    #pragma unroll
    for (int i = e; i < HASH_SZ; i += EE) {
        s_slotkey[i] = -1;
        s_slotval[i] = -1;
    }

    const int2 rc  = reinterpret_cast<const int2*>(edge_index)[(size_t)b * EE + e];
    const int key  = (rc.x << 9) | rc.y;     // r, c in [0, 512)
    const int attr = edge_attr[b * EE + e];
    __syncthreads();

    unsigned h = (((unsigned)key * 2654435761u) >> 20) & (HASH_SZ - 1);
    while (true) {
        int old = atomicCAS(&s_slotkey[h], -1, key);
        if (old == -1 || old == key) { atomicMax(&s_slotval[h], e); break; }
        h = (h + 1) & (HASH_SZ - 1);
    }
    __syncthreads();

    const bool live = (s_slotval[h] == e);   // last scatter write wins

    float corr = 0.0f;
    if (live && attr != 0) {
        const size_t cell = (size_t)b * POS_PER_B + (size_t)rc.x * NNDIM + rc.y;
        if (mask[cell]) {
            const float* p = adj + (size_t)b * CC * POS_PER_B
                           + (size_t)rc.x * NNDIM + rc.y;
            corr = p[0] - p[(size_t)attr * POS_PER_B];   // swap x_0 -> x_attr
        }
    }

    #pragma unroll
    for (int off = 16; off > 0; off >>= 1)
        corr += __shfl_down_sync(0xFFFFFFFFu, corr, off);
    __shared__ float r_sum[32];
    const int lane = e & 31, warp = e >> 5;
    if (lane == 0) r_sum[warp] = corr;
    __syncthreads();
    if (warp == 0) {
        float v = r_sum[lane];
        #pragma unroll
        for (int off = 16; off > 0; off >>= 1)
            v += __shfl_down_sync(0xFFFFFFFFu, v, off);
        if (lane == 0) atomicAdd(&g_sum[b], (double)v);
    }
}

// ---------------------------------------------------------------------------
// 2) Persistent streaming loss kernel — STATIC schedule + cross-iteration
//    SOFTWARE PIPELINE at half-class granularity.
//    Block -> batch b = blockIdx.x & 7, slot bb = blockIdx.x >> 3 (55 slots).
//    Groups: g = bb*256 + t + i*14080 (static stride; no atomics, no syncs).
//    Classes split LOW(0-7)/HIGH(8-15), double-buffered in registers:
//        load LOW(g0)
//        loop: load HIGH(g) ; compute LOW (exp + masked -x0/cnt)
//              load LOW(g+stride) ; compute HIGH (exp + log + masked)
//    so every MUFU burst runs with >=8 LDG.128 outstanding — the memory
//    pipe never drains. The label-0 subtraction folds into the LOW phase,
//    so no staged value must survive a phase boundary.
//    Register accumulation; one reduction + atomic pair at retirement;
//    last retiring block (ticket) computes the final batch-mean scalar.
// ---------------------------------------------------------------------------
__global__ void __launch_bounds__(256, 3) loss_kernel(
        const float* __restrict__ adj,
        const unsigned char* __restrict__ mask,
        float* __restrict__ out) {
    const int t    = threadIdx.x;
    const int lane = t & 31, warp = t >> 5;
    const int b    = blockIdx.x & (BB - 1);
    const int bb   = blockIdx.x >> 3;        // 0..54 slot within batch
    __shared__ float r_sum[8];
    __shared__ float r_cnt[8];

    const float* adj_b = adj + (size_t)b * CC * POS_PER_B;
    const unsigned char* mask_b = mask + (size_t)b * POS_PER_B;

    float sum = 0.0f, cnt = 0.0f;

    float4 lo[8], hi[8];
    uchar4 m4;

    int g = bb * 256 + t;
    bool valid = (g < GROUPS_PER_B);

    // Prologue: first LOW half + mask.
    if (valid) {
        const float4* base = reinterpret_cast<const float4*>(adj_b + (g << 2));
        m4 = *reinterpret_cast<const uchar4*>(mask_b + (g << 2));
        #pragma unroll
        for (int c = 0; c < 8; c++)
            lo[c] = __ldcs(base + (size_t)c * (POS_PER_B / 4));
    }

    while (valid) {
        const float4* base = reinterpret_cast<const float4*>(adj_b + (g << 2));

        // ---- load HIGH(g): 8 independent LDG.128 in flight ----
        #pragma unroll
        for (int c = 0; c < 8; c++)
            hi[c] = __ldcs(base + (size_t)(c + 8) * (POS_PER_B / 4));

        // ---- compute LOW: 32 exp; fold masked -x0 and cnt here ----
        float s0 = __expf(lo[0].x), s1 = __expf(lo[0].y);
        float s2 = __expf(lo[0].z), s3 = __expf(lo[0].w);
        if (m4.x) { sum -= lo[0].x; cnt += 1.0f; }
        if (m4.y) { sum -= lo[0].y; cnt += 1.0f; }
        if (m4.z) { sum -= lo[0].z; cnt += 1.0f; }
        if (m4.w) { sum -= lo[0].w; cnt += 1.0f; }
        #pragma unroll
        for (int c = 1; c < 8; c++) {
            s0 += __expf(lo[c].x); s1 += __expf(lo[c].y);
            s2 += __expf(lo[c].z); s3 += __expf(lo[c].w);
        }

        // ---- load LOW(g+stride) + its mask (overlaps HIGH compute) ----
        const int gn = g + BSTRIDE;
        const bool vn = (gn < GROUPS_PER_B);
        const uchar4 m4cur = m4;              // current mask for HIGH phase
        if (vn) {
            const float4* nbase =
                reinterpret_cast<const float4*>(adj_b + (gn << 2));
            m4 = *reinterpret_cast<const uchar4*>(mask_b + (gn << 2));
            #pragma unroll
            for (int c = 0; c < 8; c++)
                lo[c] = __ldcs(nbase + (size_t)c * (POS_PER_B / 4));
        }

        // ---- compute HIGH: 32 exp + 4 log, masked accumulate ----
        #pragma unroll
        for (int c = 0; c < 8; c++) {
            s0 += __expf(hi[c].x); s1 += __expf(hi[c].y);
            s2 += __expf(hi[c].z); s3 += __expf(hi[c].w);
        }
        if (m4cur.x) sum += __logf(s0);
        if (m4cur.y) sum += __logf(s1);
        if (m4cur.z) sum += __logf(s2);
        if (m4cur.w) sum += __logf(s3);

        g = gn;
        valid = vn;
    }

    // ---- single retirement reduction (all 8 warps share batch b) ----
    #pragma unroll
    for (int off = 16; off > 0; off >>= 1) {
        sum += __shfl_down_sync(0xFFFFFFFFu, sum, off);
        cnt += __shfl_down_sync(0xFFFFFFFFu, cnt, off);
    }
    if (lane == 0) { r_sum[warp] = sum; r_cnt[warp] = cnt; }
    __syncthreads();

    if (t == 0) {
        float bs = 0.0f, bc = 0.0f;
        #pragma unroll
        for (int w = 0; w < 8; w++) { bs += r_sum[w]; bc += r_cnt[w]; }
        atomicAdd(&g_sum[b], (double)bs);
        atomicAdd(&g_cnt[b], (double)bc);

        __threadfence();
        const unsigned ticket = atomicAdd(&g_done, 1u);
        if (ticket == PBLK - 1) {
            double acc = 0.0;
            #pragma unroll
            for (int i = 0; i < BB; i++) {
                volatile double* vs = g_sum;
                volatile double* vc = g_cnt;
                double c = vc[i];
                if (c < 1.0) c = 1.0;
                acc += vs[i] / c;
            }
            out[0] = (float)(acc / (double)BB);
        }
    }
}

// ---------------------------------------------------------------------------
// kernel_launch — inputs (metadata order): adj f32 [B,C,N,N], mask bool(u8)
// [B,N,N], edge_index i32 [B,E,2], edge_attr i32 [B,E]. Output: 1 fp32 scalar.
// ---------------------------------------------------------------------------
extern "C" void kernel_launch(void* const* d_in, const int* in_sizes, int n_in,
                              void* d_out, int out_size) {
    const float*         adj        = (const float*)d_in[0];
    const unsigned char* mask       = (const unsigned char*)d_in[1];
    const int*           edge_index = (const int*)d_in[2];
    const int*           edge_attr  = (const int*)d_in[3];
    float*               out        = (float*)d_out;

    corr_kernel<<<BB, EE>>>(adj, mask, edge_index, edge_attr);
    loss_kernel<<<PBLK, 256>>>(adj, mask, out);
}